// round 16
// baseline (speedup 1.0000x reference)
#include <cuda_runtime.h>
#include <cuda_fp16.h>
#include <math.h>

#define NB 128
#define NH 256
#define NW 256
#define NC 64
#define GS1 272   // 4B-unit group stride, passes 1/3 (≡16 mod 32: complementary banks)
#define GSP 290   // 4B-unit group stride, pass 2    (≡2  mod 32)

// 128*256*256 complex half = 32 MB static scratch (allocation-free)
__device__ __half2 g_scratch[(size_t)NB * NH * NW];

__device__ __forceinline__ float2 cadd(float2 a, float2 b){ return make_float2(a.x+b.x, a.y+b.y); }
__device__ __forceinline__ float2 csub(float2 a, float2 b){ return make_float2(a.x-b.x, a.y-b.y); }
__device__ __forceinline__ float2 cmul(float2 a, float2 b){
    return make_float2(fmaf(a.x, b.x, -a.y*b.y), fmaf(a.x, b.y, a.y*b.x));
}
template<int SIGN>
__device__ __forceinline__ float2 rot90(float2 a){   // × (-i) fwd, (+i) inv
    return (SIGN < 0) ? make_float2(a.y, -a.x) : make_float2(-a.y, a.x);
}
template<int SIGN>
__device__ __forceinline__ float2 cmulw(float2 a, float wr, float wi_f){
    float wi = (SIGN < 0) ? wi_f : -wi_f;
    return make_float2(fmaf(a.x, wr, -a.y*wi), fmaf(a.x, wi, a.y*wr));
}
__device__ __forceinline__ __half2 f2h(float2 v){ return __float22half2_rn(v); }
__device__ __forceinline__ float2 h2f(__half2 v){ return __half22float2(v); }
__device__ __forceinline__ unsigned pk(float2 v){
    __half2 h = __float22half2_rn(v);
    return *reinterpret_cast<unsigned*>(&h);
}
__device__ __forceinline__ float2 upk(unsigned u){
    __half2 h = *reinterpret_cast<__half2*>(&u);
    return __half22float2(h);
}

// Fully-unrolled 16-point DFT in registers, all twiddles as immediates.
template<int SIGN>
__device__ __forceinline__ void fft16(float2* r){
    const float C1 = 0.92387953251f, S1 = 0.38268343236f, C2 = 0.70710678119f;
    float2 v[16];
#pragma unroll
    for (int p = 0; p < 4; ++p){
        float2 a=r[p], b=r[p+4], c=r[p+8], d=r[p+12];
        float2 t0=cadd(a,c), t1=csub(a,c), t2=cadd(b,d);
        float2 t3=rot90<SIGN>(csub(b,d));
        float2 u0=cadd(t0,t2), u1=cadd(t1,t3), u2=csub(t0,t2), u3=csub(t1,t3);
        if (p == 1){
            u1 = cmulw<SIGN>(u1,  C1, -S1);
            u2 = cmulw<SIGN>(u2,  C2, -C2);
            u3 = cmulw<SIGN>(u3,  S1, -C1);
        } else if (p == 2){
            u1 = cmulw<SIGN>(u1,  C2, -C2);
            u2 = rot90<SIGN>(u2);
            u3 = cmulw<SIGN>(u3, -C2, -C2);
        } else if (p == 3){
            u1 = cmulw<SIGN>(u1,  S1, -C1);
            u2 = cmulw<SIGN>(u2, -C2, -C2);
            u3 = cmulw<SIGN>(u3, -C1,  S1);
        }
        v[p]=u0; v[4+p]=u1; v[8+p]=u2; v[12+p]=u3;
    }
#pragma unroll
    for (int m = 0; m < 4; ++m){
        float2 a=v[4*m], b=v[4*m+1], c=v[4*m+2], d=v[4*m+3];
        float2 t0=cadd(a,c), t1=csub(a,c), t2=cadd(b,d);
        float2 t3=rot90<SIGN>(csub(b,d));
        r[m]    = cadd(t0,t2);
        r[4+m]  = cadd(t1,t3);
        r[8+m]  = csub(t0,t2);
        r[12+m] = csub(t1,t3);
    }
}

// Build the 16x16 twiddle table T[n1][k] = exp(-2*pi*i*n1*k/256), stride 17.
// 256 threads, one entry each. Callers __syncthreads() before use.
__device__ __forceinline__ void build_twtbl(float2* tbl, int t){
    int tn = t >> 4, tk = t & 15;
    float sn, cs;
    __sincosf((float)(tn * tk) * -0.024543692606170259f /* -pi/128 */, &sn, &cs);
    tbl[tn*17 + tk] = make_float2(cs, sn);
}

// r[k] *= w^k via table row (forward values; conjugate applied for inverse).
template<int SIGN>
__device__ __forceinline__ void twiddle_tbl(float2* r, const float2* row){
#pragma unroll
    for (int k = 1; k < 16; ++k){
        float2 w = row[k];
        if (SIGN > 0) w.y = -w.y;
        r[k] = cmul(r[k], w);
    }
}

// ---------------------------------------------------------------------------
// Pass 1: forward FFT along W. 16 rows/block, 256 threads. fp16 smem transpose.
// ---------------------------------------------------------------------------
__global__ void __launch_bounds__(256) k_rowfft(const float* __restrict__ x){
    __shared__ unsigned s[16*GS1];
    __shared__ float2 stw[16*17];
    int t = threadIdx.x;
    build_twtbl(stw, t);
    int n1 = t & 15, wl = t >> 4;
    int row = blockIdx.x * 16 + wl;
    const float* xr = x + (size_t)row * NW;
    float2 r[16];
#pragma unroll
    for (int n2 = 0; n2 < 16; ++n2) r[n2] = make_float2(xr[n1 + 16*n2], 0.0f);
    fft16<-1>(r);                         // over n2 -> regs k2
    __syncthreads();                      // table visible
    twiddle_tbl<-1>(r, stw + n1*17);
    unsigned* sg = s + wl*GS1;
#pragma unroll
    for (int k2 = 0; k2 < 16; ++k2) sg[n1*17 + k2] = pk(r[k2]);
    __syncwarp();
#pragma unroll
    for (int i = 0; i < 16; ++i) r[i] = upk(sg[i*17 + n1]);  // role: k2 = n1
    fft16<-1>(r);                         // over n1 -> regs k1: X[16*k1 + n1]
    __half2* gp = g_scratch + (size_t)row * NW;
#pragma unroll
    for (int k1 = 0; k1 < 16; ++k1) gp[n1 + 16*k1] = f2h(r[k1]);
}

// ---------------------------------------------------------------------------
// Pass 2: fwd FFT along H + mask (fftshift folded, 1/256 folded into mask) +
// inv FFT along H, fused, in-place. fp16 smem transposes (GSP stride).
// Twiddle rows indexed by u -> broadcast LDS (all 16 lanes share u).
// ---------------------------------------------------------------------------
__global__ void __launch_bounds__(256) k_colfft_mask(const float* __restrict__ pi,
                                                     const int* __restrict__ cid){
    __shared__ unsigned s[16*GSP];
    __shared__ float sPI[NC];
    __shared__ float2 stw[16*17];
    int t = threadIdx.x;
    build_twtbl(stw, t);
    int b  = blockIdx.y;
    int w0 = blockIdx.x * 16;
    const float inv256 = 1.0f / 256.0f;
    if (t < NC) sPI[t] = pi[((b + 64) & 127) * NC + t] * inv256;  // pre-scaled
    int w = t & 15, u = t >> 4;
    const float2* trow = stw + u*17;
    __half2* g = g_scratch + (size_t)b * NH * NW + w0;
    float2 r[16];
#pragma unroll
    for (int n2 = 0; n2 < 16; ++n2) r[n2] = h2f(g[(u + 16*n2)*NW + w]);
    // hoisted cid loads
    int wp = (w0 + w + 128) & 255;
    int cc[16];
#pragma unroll
    for (int k1 = 0; k1 < 16; ++k1){
        int hp = (16*k1 + u + 128) & 255;
        cc[k1] = __ldg(&cid[hp*NW + wp]);
    }
    fft16<-1>(r);                         // over n2 -> k2
    __syncthreads();                      // table + sPI visible
    twiddle_tbl<-1>(r, trow);
    unsigned* sg = s + w*GSP;
#pragma unroll
    for (int k2 = 0; k2 < 16; ++k2) sg[u*17 + k2] = pk(r[k2]);
    __syncthreads();
#pragma unroll
    for (int i = 0; i < 16; ++i) r[i] = upk(sg[i*17 + u]);   // role: k2 = u
    fft16<-1>(r);                         // over n1 -> k1: F[16*k1 + u]
    // mask (1/256 H-normalization folded in): keeps fp16 smem in range
#pragma unroll
    for (int k1 = 0; k1 < 16; ++k1){
        float m = (cc[k1] < NC) ? sPI[cc[k1]] : inv256;
        r[k1].x *= m; r[k1].y *= m;
    }
    fft16<1>(r);                          // over k1 -> m1
    twiddle_tbl<1>(r, trow);
    __syncthreads();
#pragma unroll
    for (int m1 = 0; m1 < 16; ++m1) sg[u*17 + m1] = pk(r[m1]);
    __syncthreads();
#pragma unroll
    for (int i = 0; i < 16; ++i) r[i] = upk(sg[i*17 + u]);   // role: m1 = u
    fft16<1>(r);                          // over k2 -> m2: y[m1 + 16*m2]
#pragma unroll
    for (int m2 = 0; m2 < 16; ++m2)
        g[(u + 16*m2)*NW + w] = f2h(r[m2]);
}

// ---------------------------------------------------------------------------
// Pass 3: inverse FFT along W (1/256) + magnitude + 3 channels + pi tail.
// fp16 smem transpose (GS1 stride).
// ---------------------------------------------------------------------------
__global__ void __launch_bounds__(256) k_irow_out(const float* __restrict__ x,
                                                  const float* __restrict__ pi,
                                                  float* __restrict__ out){
    __shared__ unsigned s[16*GS1];
    __shared__ float2 stw[16*17];
    int t = threadIdx.x;
    build_twtbl(stw, t);
    int u = t & 15, rl = t >> 4;
    int row = blockIdx.x * 16 + rl;
    int b = row >> 8, h = row & 255;
    const __half2* gp = g_scratch + (size_t)row * NW;
    float2 r[16];
#pragma unroll
    for (int k1 = 0; k1 < 16; ++k1) r[k1] = h2f(gp[u + 16*k1]);
    fft16<1>(r);                          // over k1 -> m1
    __syncthreads();                      // table visible
    twiddle_tbl<1>(r, stw + u*17);
    unsigned* sg = s + rl*GS1;
#pragma unroll
    for (int m1 = 0; m1 < 16; ++m1) sg[u*17 + m1] = pk(r[m1]);
    __syncwarp();
#pragma unroll
    for (int i = 0; i < 16; ++i) r[i] = upk(sg[i*17 + u]);   // role: m1 = u
    fft16<1>(r);                          // over k2 -> m2: y[u + 16*m2]
    const float sc = 1.0f / 256.0f;       // W-inverse normalization
    const float* xr = x + (size_t)row * NW;
    size_t base = ((size_t)(b*3) * NH + h) * NW;
#pragma unroll
    for (int m2 = 0; m2 < 16; ++m2){
        int m = u + 16*m2;
        float2 v = r[m2];
        float s2 = fmaf(v.x, v.x, v.y*v.y);
        float mag = s2 * __frsqrt_rn(fmaxf(s2, 1e-37f)) * sc;
        float xv = xr[m];
        out[base + m]                      = xv;
        out[base + (size_t)NH*NW + m]      = mag;
        out[base + 2*(size_t)NH*NW + m]    = fabsf(mag - xv);
    }
    if (blockIdx.x == 0){
        for (int i = t; i < NB * NC; i += 256)
            out[(size_t)NB * 3 * NH * NW + i] = pi[i];
    }
}

extern "C" void kernel_launch(void* const* d_in, const int* in_sizes, int n_in,
                              void* d_out, int out_size) {
    const float* x  = (const float*)d_in[0];   // [128,256,256] f32
    const float* pi = (const float*)d_in[1];   // [128,64]      f32
    const int* cid  = (const int*)d_in[2];     // [256,256]     i32
    float* out = (float*)d_out;                // [128,3,256,256] + [128,64]

    k_rowfft<<<(NB*NH)/16, 256>>>(x);
    k_colfft_mask<<<dim3(NW/16, NB), 256>>>(pi, cid);
    k_irow_out<<<(NB*NH)/16, 256>>>(x, pi, out);
}

// round 17
// speedup vs baseline: 1.0383x; 1.0383x over previous
#include <cuda_runtime.h>
#include <cuda_fp16.h>
#include <math.h>

#define NB 128
#define NH 256
#define NW 256
#define NC 64
#define GS1 272   // 4B-unit group stride, passes 1/3 (≡16 mod 32: complementary banks)
#define GSP 290   // 4B-unit group stride, pass 2    (≡2  mod 32)

// 128*256*256 complex half = 32 MB static scratch (allocation-free)
__device__ __half2 g_scratch[(size_t)NB * NH * NW];

__device__ __forceinline__ float2 cadd(float2 a, float2 b){ return make_float2(a.x+b.x, a.y+b.y); }
__device__ __forceinline__ float2 csub(float2 a, float2 b){ return make_float2(a.x-b.x, a.y-b.y); }
__device__ __forceinline__ float2 cmul(float2 a, float2 b){
    return make_float2(fmaf(a.x, b.x, -a.y*b.y), fmaf(a.x, b.y, a.y*b.x));
}
template<int SIGN>
__device__ __forceinline__ float2 rot90(float2 a){   // × (-i) fwd, (+i) inv
    return (SIGN < 0) ? make_float2(a.y, -a.x) : make_float2(-a.y, a.x);
}
template<int SIGN>
__device__ __forceinline__ float2 cmulw(float2 a, float wr, float wi_f){
    float wi = (SIGN < 0) ? wi_f : -wi_f;
    return make_float2(fmaf(a.x, wr, -a.y*wi), fmaf(a.x, wi, a.y*wr));
}
__device__ __forceinline__ __half2 f2h(float2 v){ return __float22half2_rn(v); }
__device__ __forceinline__ float2 h2f(__half2 v){ return __half22float2(v); }
__device__ __forceinline__ unsigned pk(float2 v){
    __half2 h = __float22half2_rn(v);
    return *reinterpret_cast<unsigned*>(&h);
}
__device__ __forceinline__ float2 upk(unsigned u){
    __half2 h = *reinterpret_cast<__half2*>(&u);
    return __half22float2(h);
}

// Fully-unrolled 16-point DFT in registers, all twiddles as immediates.
template<int SIGN>
__device__ __forceinline__ void fft16(float2* r){
    const float C1 = 0.92387953251f, S1 = 0.38268343236f, C2 = 0.70710678119f;
    float2 v[16];
#pragma unroll
    for (int p = 0; p < 4; ++p){
        float2 a=r[p], b=r[p+4], c=r[p+8], d=r[p+12];
        float2 t0=cadd(a,c), t1=csub(a,c), t2=cadd(b,d);
        float2 t3=rot90<SIGN>(csub(b,d));
        float2 u0=cadd(t0,t2), u1=cadd(t1,t3), u2=csub(t0,t2), u3=csub(t1,t3);
        if (p == 1){
            u1 = cmulw<SIGN>(u1,  C1, -S1);
            u2 = cmulw<SIGN>(u2,  C2, -C2);
            u3 = cmulw<SIGN>(u3,  S1, -C1);
        } else if (p == 2){
            u1 = cmulw<SIGN>(u1,  C2, -C2);
            u2 = rot90<SIGN>(u2);
            u3 = cmulw<SIGN>(u3, -C2, -C2);
        } else if (p == 3){
            u1 = cmulw<SIGN>(u1,  S1, -C1);
            u2 = cmulw<SIGN>(u2, -C2, -C2);
            u3 = cmulw<SIGN>(u3, -C1,  S1);
        }
        v[p]=u0; v[4+p]=u1; v[8+p]=u2; v[12+p]=u3;
    }
#pragma unroll
    for (int m = 0; m < 4; ++m){
        float2 a=v[4*m], b=v[4*m+1], c=v[4*m+2], d=v[4*m+3];
        float2 t0=cadd(a,c), t1=csub(a,c), t2=cadd(b,d);
        float2 t3=rot90<SIGN>(csub(b,d));
        r[m]    = cadd(t0,t2);
        r[4+m]  = cadd(t1,t3);
        r[8+m]  = csub(t0,t2);
        r[12+m] = csub(t1,t3);
    }
}

// r[k] *= w^k, w = exp(SIGN*2*pi*i*n1/256). MUFU base + split even/odd chains.
template<int SIGN>
__device__ __forceinline__ void twiddle_pows(float2* r, int n1){
    float sn, cs;
    __sincosf((float)n1 * 0.024543692606170259f /* pi/128 */, &sn, &cs);
    float2 w1 = make_float2(cs, (SIGN < 0) ? -sn : sn);
    float2 w2 = cmul(w1, w1);
    float2 e = w2;
    float2 o = cmul(w1, w2);
    r[1] = cmul(r[1], w1);
    r[2] = cmul(r[2], e);
    r[3] = cmul(r[3], o);
#pragma unroll
    for (int k = 2; k < 8; ++k){
        e = cmul(e, w2);
        o = cmul(o, w2);
        r[2*k]   = cmul(r[2*k],   e);
        r[2*k+1] = cmul(r[2*k+1], o);
    }
}

// ---------------------------------------------------------------------------
// Pass 1: forward FFT along W. 16 rows/block, 256 threads. fp16 smem transpose.
// Also writes output channel 0 (the x passthrough) while x is in registers.
// ---------------------------------------------------------------------------
__global__ void __launch_bounds__(256) k_rowfft(const float* __restrict__ x,
                                                float* __restrict__ out){
    __shared__ unsigned s[16*GS1];
    int t = threadIdx.x;
    int n1 = t & 15, wl = t >> 4;
    int row = blockIdx.x * 16 + wl;
    int b = row >> 8, h = row & 255;
    const float* xr = x + (size_t)row * NW;
    float* o0 = out + ((size_t)(b*3) * NH + h) * NW;
    float2 r[16];
#pragma unroll
    for (int n2 = 0; n2 < 16; ++n2){
        float xv = xr[n1 + 16*n2];
        r[n2] = make_float2(xv, 0.0f);
        o0[n1 + 16*n2] = xv;              // channel 0 passthrough
    }
    fft16<-1>(r);                         // over n2 -> regs k2
    twiddle_pows<-1>(r, n1);
    unsigned* sg = s + wl*GS1;
#pragma unroll
    for (int k2 = 0; k2 < 16; ++k2) sg[n1*17 + k2] = pk(r[k2]);
    __syncwarp();
#pragma unroll
    for (int i = 0; i < 16; ++i) r[i] = upk(sg[i*17 + n1]);  // role: k2 = n1
    fft16<-1>(r);                         // over n1 -> regs k1: X[16*k1 + n1]
    __half2* gp = g_scratch + (size_t)row * NW;
#pragma unroll
    for (int k1 = 0; k1 < 16; ++k1) gp[n1 + 16*k1] = f2h(r[k1]);
}

// ---------------------------------------------------------------------------
// Pass 2: fwd FFT along H + mask (fftshift folded, 1/256 folded into mask) +
// inv FFT along H, fused, in-place. fp16 smem transposes, DOUBLE-BUFFERED:
// transpose 2 uses the second smem half, removing the WAR barrier (4 -> 2 syncs).
// ---------------------------------------------------------------------------
__global__ void __launch_bounds__(256) k_colfft_mask(const float* __restrict__ pi,
                                                     const int* __restrict__ cid){
    __shared__ unsigned s[2*16*GSP];
    __shared__ float sPI[NC];
    int t = threadIdx.x;
    int b  = blockIdx.y;
    int w0 = blockIdx.x * 16;
    const float inv256 = 1.0f / 256.0f;
    if (t < NC) sPI[t] = pi[((b + 64) & 127) * NC + t] * inv256;  // pre-scaled
    int w = t & 15, u = t >> 4;
    __half2* g = g_scratch + (size_t)b * NH * NW + w0;
    float2 r[16];
#pragma unroll
    for (int n2 = 0; n2 < 16; ++n2) r[n2] = h2f(g[(u + 16*n2)*NW + w]);
    // hoisted cid loads
    int wp = (w0 + w + 128) & 255;
    int cc[16];
#pragma unroll
    for (int k1 = 0; k1 < 16; ++k1){
        int hp = (16*k1 + u + 128) & 255;
        cc[k1] = __ldg(&cid[hp*NW + wp]);
    }
    fft16<-1>(r);                         // over n2 -> k2
    twiddle_pows<-1>(r, u);
    unsigned* sgA = s + w*GSP;
#pragma unroll
    for (int k2 = 0; k2 < 16; ++k2) sgA[u*17 + k2] = pk(r[k2]);
    __syncthreads();                      // T1 visible; also covers sPI
#pragma unroll
    for (int i = 0; i < 16; ++i) r[i] = upk(sgA[i*17 + u]);  // role: k2 = u
    fft16<-1>(r);                         // over n1 -> k1: F[16*k1 + u]
    // mask (1/256 H-normalization folded in): keeps fp16 smem in range
#pragma unroll
    for (int k1 = 0; k1 < 16; ++k1){
        float m = (cc[k1] < NC) ? sPI[cc[k1]] : inv256;
        r[k1].x *= m; r[k1].y *= m;
    }
    fft16<1>(r);                          // over k1 -> m1
    twiddle_pows<1>(r, u);
    unsigned* sgB = s + 16*GSP + w*GSP;   // second buffer: no WAR barrier needed
#pragma unroll
    for (int m1 = 0; m1 < 16; ++m1) sgB[u*17 + m1] = pk(r[m1]);
    __syncthreads();                      // T2 visible
#pragma unroll
    for (int i = 0; i < 16; ++i) r[i] = upk(sgB[i*17 + u]);  // role: m1 = u
    fft16<1>(r);                          // over k2 -> m2: y[m1 + 16*m2]
#pragma unroll
    for (int m2 = 0; m2 < 16; ++m2)
        g[(u + 16*m2)*NW + w] = f2h(r[m2]);
}

// ---------------------------------------------------------------------------
// Pass 3: inverse FFT along W (1/256) + magnitude + channels 1,2 + pi tail.
// (channel 0 is written by pass 1.)
// ---------------------------------------------------------------------------
__global__ void __launch_bounds__(256) k_irow_out(const float* __restrict__ x,
                                                  const float* __restrict__ pi,
                                                  float* __restrict__ out){
    __shared__ unsigned s[16*GS1];
    int t = threadIdx.x;
    int u = t & 15, rl = t >> 4;
    int row = blockIdx.x * 16 + rl;
    int b = row >> 8, h = row & 255;
    const __half2* gp = g_scratch + (size_t)row * NW;
    float2 r[16];
#pragma unroll
    for (int k1 = 0; k1 < 16; ++k1) r[k1] = h2f(gp[u + 16*k1]);
    fft16<1>(r);                          // over k1 -> m1
    twiddle_pows<1>(r, u);
    unsigned* sg = s + rl*GS1;
#pragma unroll
    for (int m1 = 0; m1 < 16; ++m1) sg[u*17 + m1] = pk(r[m1]);
    __syncwarp();
#pragma unroll
    for (int i = 0; i < 16; ++i) r[i] = upk(sg[i*17 + u]);   // role: m1 = u
    fft16<1>(r);                          // over k2 -> m2: y[u + 16*m2]
    const float sc = 1.0f / 256.0f;       // W-inverse normalization
    const float* xr = x + (size_t)row * NW;
    size_t base = ((size_t)(b*3) * NH + h) * NW;
#pragma unroll
    for (int m2 = 0; m2 < 16; ++m2){
        int m = u + 16*m2;
        float2 v = r[m2];
        float s2 = fmaf(v.x, v.x, v.y*v.y);
        float mag = s2 * __frsqrt_rn(fmaxf(s2, 1e-37f)) * sc;
        float xv = xr[m];
        out[base + (size_t)NH*NW + m]      = mag;
        out[base + 2*(size_t)NH*NW + m]    = fabsf(mag - xv);
    }
    if (blockIdx.x == 0){
        for (int i = t; i < NB * NC; i += 256)
            out[(size_t)NB * 3 * NH * NW + i] = pi[i];
    }
}

extern "C" void kernel_launch(void* const* d_in, const int* in_sizes, int n_in,
                              void* d_out, int out_size) {
    const float* x  = (const float*)d_in[0];   // [128,256,256] f32
    const float* pi = (const float*)d_in[1];   // [128,64]      f32
    const int* cid  = (const int*)d_in[2];     // [256,256]     i32
    float* out = (float*)d_out;                // [128,3,256,256] + [128,64]

    k_rowfft<<<(NB*NH)/16, 256>>>(x, out);
    k_colfft_mask<<<dim3(NW/16, NB), 256>>>(pi, cid);
    k_irow_out<<<(NB*NH)/16, 256>>>(x, pi, out);
}